// round 1
// baseline (speedup 1.0000x reference)
#include <cuda_runtime.h>

// Problem constants
#define BB 2
#define TT 1024
#define DD 1024
#define VV 32000
#define LL 8

// Scratch (device globals; no allocation allowed)
__device__ float g_x[BB * TT * DD];   // residual stream
__device__ float g_q[BB * TT * DD];   // Q / final-LN output (reused)
__device__ float g_k[BB * TT * DD];   // K
__device__ float g_v[BB * TT * DD];   // V
__device__ float g_a[BB * TT * TT];   // scores -> softmax weights
__device__ float g_o[BB * TT * DD];   // attention output

// ---------------------------------------------------------------------------
// Embedding + (faithfully buggy) positional encoding: x[b,t,:] = embed[src[b,t]] + pe[b,0,:]
// ---------------------------------------------------------------------------
__global__ void embed_pe_kernel(const int* __restrict__ src,
                                const float* __restrict__ pe,
                                const float* __restrict__ embed,
                                float* __restrict__ x)
{
    int row = blockIdx.x;            // 0 .. B*T-1
    int b   = row >> 10;             // T = 1024
    long tok = src[row];
    const float4* e = reinterpret_cast<const float4*>(embed + tok * (long)DD);
    const float4* p = reinterpret_cast<const float4*>(pe + (long)b * DD);
    float4* xo = reinterpret_cast<float4*>(x + (long)row * DD);
    int i = threadIdx.x;             // 256 threads * float4 = 1024 floats
    float4 ev = e[i], pv = p[i];
    xo[i] = make_float4(ev.x + pv.x, ev.y + pv.y, ev.z + pv.z, ev.w + pv.w);
}

// ---------------------------------------------------------------------------
// 128x128x16 SGEMM, 256 threads, 8x8 per-thread microtile.
// BKMAJ=true : C[M,N] = A[M,K] * B[N,K]^T  (NT; both operands K-contiguous)
// BKMAJ=false: C[M,N] = A[M,K] * B[K,N]    (NN; B is N-contiguous)
// CAUSAL=true: skip blocks strictly above the diagonal (scores GEMM).
// All dims are multiples of the tile sizes -> no bounds checks.
// ---------------------------------------------------------------------------
template <bool BKMAJ, bool CAUSAL>
__global__ __launch_bounds__(256, 2)
void sgemm128(const float* __restrict__ A, const float* __restrict__ B,
              const float* __restrict__ bias, float* __restrict__ C,
              int K, int lda, int ldb, int ldc,
              long aBatch, long bBatch, long cBatch)
{
    if (CAUSAL && blockIdx.x > blockIdx.y) return;
    A += blockIdx.z * aBatch;
    B += blockIdx.z * bBatch;
    C += blockIdx.z * cBatch;

    __shared__ float As[16][128];
    __shared__ float Bs[16][128];

    const int tid = threadIdx.x;
    const int m0 = blockIdx.y * 128;
    const int n0 = blockIdx.x * 128;
    const int tr = (tid >> 4) << 3;   // row offset in tile (0..120)
    const int tc = (tid & 15) << 3;   // col offset in tile (0..120)

    float acc[8][8];
#pragma unroll
    for (int i = 0; i < 8; i++)
#pragma unroll
        for (int j = 0; j < 8; j++) acc[i][j] = 0.f;

    for (int k0 = 0; k0 < K; k0 += 16) {
        // A tile: 128 rows x 16 k, K-contiguous, transposed into As[k][m]
#pragma unroll
        for (int f = tid; f < 512; f += 256) {
            int row = f >> 2, kk = (f & 3) << 2;
            float4 val = *reinterpret_cast<const float4*>(A + (long)(m0 + row) * lda + k0 + kk);
            As[kk + 0][row] = val.x;
            As[kk + 1][row] = val.y;
            As[kk + 2][row] = val.z;
            As[kk + 3][row] = val.w;
        }
        if (BKMAJ) {
#pragma unroll
            for (int f = tid; f < 512; f += 256) {
                int row = f >> 2, kk = (f & 3) << 2;
                float4 val = *reinterpret_cast<const float4*>(B + (long)(n0 + row) * ldb + k0 + kk);
                Bs[kk + 0][row] = val.x;
                Bs[kk + 1][row] = val.y;
                Bs[kk + 2][row] = val.z;
                Bs[kk + 3][row] = val.w;
            }
        } else {
#pragma unroll
            for (int f = tid; f < 512; f += 256) {
                int kr = f >> 5, nn = (f & 31) << 2;
                *reinterpret_cast<float4*>(&Bs[kr][nn]) =
                    *reinterpret_cast<const float4*>(B + (long)(k0 + kr) * ldb + n0 + nn);
            }
        }
        __syncthreads();

#pragma unroll
        for (int k = 0; k < 16; k++) {
            float a[8], b[8];
            *reinterpret_cast<float4*>(a)     = *reinterpret_cast<const float4*>(&As[k][tr]);
            *reinterpret_cast<float4*>(a + 4) = *reinterpret_cast<const float4*>(&As[k][tr + 4]);
            *reinterpret_cast<float4*>(b)     = *reinterpret_cast<const float4*>(&Bs[k][tc]);
            *reinterpret_cast<float4*>(b + 4) = *reinterpret_cast<const float4*>(&Bs[k][tc + 4]);
#pragma unroll
            for (int i = 0; i < 8; i++)
#pragma unroll
                for (int j = 0; j < 8; j++)
                    acc[i][j] = fmaf(a[i], b[j], acc[i][j]);
        }
        __syncthreads();
    }

    float bv[8];
#pragma unroll
    for (int j = 0; j < 8; j++) bv[j] = bias ? bias[n0 + tc + j] : 0.f;
#pragma unroll
    for (int i = 0; i < 8; i++) {
        float* cp = C + (long)(m0 + tr + i) * ldc + n0 + tc;
        float4 v0 = make_float4(acc[i][0] + bv[0], acc[i][1] + bv[1],
                                acc[i][2] + bv[2], acc[i][3] + bv[3]);
        float4 v1 = make_float4(acc[i][4] + bv[4], acc[i][5] + bv[5],
                                acc[i][6] + bv[6], acc[i][7] + bv[7]);
        *reinterpret_cast<float4*>(cp)     = v0;
        *reinterpret_cast<float4*>(cp + 4) = v1;
    }
}

// ---------------------------------------------------------------------------
// Causal masked softmax over a row of A[b,t,:]; writes exact zeros for s > t
// so the downstream w@V GEMM can be dense.
// ---------------------------------------------------------------------------
__global__ void softmax_kernel(float* __restrict__ A)
{
    int t = blockIdx.x;
    int b = blockIdx.y;
    float* row = A + ((long)b * TT + t) * TT;
    int n = t + 1;                         // valid entries: s in [0, t]
    int i = threadIdx.x;
    __shared__ float red[256];

    float m = -1e30f;
    for (int s = i; s < n; s += 256) m = fmaxf(m, row[s]);
    red[i] = m;
    __syncthreads();
    for (int st = 128; st > 0; st >>= 1) {
        if (i < st) red[i] = fmaxf(red[i], red[i + st]);
        __syncthreads();
    }
    m = red[0];
    __syncthreads();

    float sum = 0.f;
    for (int s = i; s < n; s += 256) {
        float e = expf(row[s] - m);
        row[s] = e;
        sum += e;
    }
    red[i] = sum;
    __syncthreads();
    for (int st = 128; st > 0; st >>= 1) {
        if (i < st) red[i] += red[i + st];
        __syncthreads();
    }
    float inv = 1.0f / red[0];

    for (int s = i; s < TT; s += 256)
        row[s] = (s < n) ? row[s] * inv : 0.0f;
}

// ---------------------------------------------------------------------------
// Custom LN (eps inside sqrt, 1e-6, biased var) + residual add into x.
// Two-pass mean/var for accuracy. One block (256 thr) per row, float4 lanes.
// ---------------------------------------------------------------------------
__global__ void ln_res_kernel(const float* __restrict__ O,
                              const float* __restrict__ w,
                              const float* __restrict__ bb,
                              float* __restrict__ X)
{
    int row = blockIdx.x;
    int i = threadIdx.x;
    const float4 o = reinterpret_cast<const float4*>(O + (long)row * DD)[i];
    float4* x4 = reinterpret_cast<float4*>(X + (long)row * DD);
    __shared__ float red[256];

    red[i] = o.x + o.y + o.z + o.w;
    __syncthreads();
    for (int st = 128; st > 0; st >>= 1) {
        if (i < st) red[i] += red[i + st];
        __syncthreads();
    }
    float mu = red[0] * (1.0f / DD);
    __syncthreads();

    float dx = o.x - mu, dy = o.y - mu, dz = o.z - mu, dw_ = o.w - mu;
    red[i] = dx * dx + dy * dy + dz * dz + dw_ * dw_;
    __syncthreads();
    for (int st = 128; st > 0; st >>= 1) {
        if (i < st) red[i] += red[i + st];
        __syncthreads();
    }
    float rstd = rsqrtf(red[0] * (1.0f / DD) + 1e-6f);

    float4 wv = reinterpret_cast<const float4*>(w)[i];
    float4 bv = reinterpret_cast<const float4*>(bb)[i];
    float4 xv = x4[i];
    xv.x += dx * rstd * wv.x + bv.x;
    xv.y += dy * rstd * wv.y + bv.y;
    xv.z += dz * rstd * wv.z + bv.z;
    xv.w += dw_ * rstd * wv.w + bv.w;
    x4[i] = xv;
}

// ---------------------------------------------------------------------------
// Final nn.LayerNorm (eps=1e-5) -> out buffer
// ---------------------------------------------------------------------------
__global__ void final_ln_kernel(const float* __restrict__ X,
                                const float* __restrict__ fw,
                                const float* __restrict__ fb,
                                float* __restrict__ Y)
{
    int row = blockIdx.x;
    int i = threadIdx.x;
    const float4 x = reinterpret_cast<const float4*>(X + (long)row * DD)[i];
    float4* y4 = reinterpret_cast<float4*>(Y + (long)row * DD);
    __shared__ float red[256];

    red[i] = x.x + x.y + x.z + x.w;
    __syncthreads();
    for (int st = 128; st > 0; st >>= 1) {
        if (i < st) red[i] += red[i + st];
        __syncthreads();
    }
    float mu = red[0] * (1.0f / DD);
    __syncthreads();

    float dx = x.x - mu, dy = x.y - mu, dz = x.z - mu, dw_ = x.w - mu;
    red[i] = dx * dx + dy * dy + dz * dz + dw_ * dw_;
    __syncthreads();
    for (int st = 128; st > 0; st >>= 1) {
        if (i < st) red[i] += red[i + st];
        __syncthreads();
    }
    float rstd = rsqrtf(red[0] * (1.0f / DD) + 1e-5f);

    float4 wv = reinterpret_cast<const float4*>(fw)[i];
    float4 bv = reinterpret_cast<const float4*>(fb)[i];
    y4[i] = make_float4(dx * rstd * wv.x + bv.x,
                        dy * rstd * wv.y + bv.y,
                        dz * rstd * wv.z + bv.z,
                        dw_ * rstd * wv.w + bv.w);
}

// ---------------------------------------------------------------------------
// Launch
// ---------------------------------------------------------------------------
extern "C" void kernel_launch(void* const* d_in, const int* in_sizes, int n_in,
                              void* d_out, int out_size)
{
    const int*   src = (const int*)d_in[0];
    const float* pe  = (const float*)d_in[1];
    const float* emb = (const float*)d_in[2];
    const float* qw  = (const float*)d_in[3];
    const float* qb  = (const float*)d_in[4];
    const float* kw  = (const float*)d_in[5];
    const float* kb  = (const float*)d_in[6];
    const float* vw  = (const float*)d_in[7];
    const float* vb  = (const float*)d_in[8];
    const float* lnw = (const float*)d_in[9];
    const float* lnb = (const float*)d_in[10];
    const float* fw  = (const float*)d_in[11];
    const float* fb  = (const float*)d_in[12];
    const float* dw  = (const float*)d_in[13];
    const float* db  = (const float*)d_in[14];
    float* out = (float*)d_out;

    void *px, *pq, *pk, *pv, *pa, *po;
    cudaGetSymbolAddress(&px, g_x);
    cudaGetSymbolAddress(&pq, g_q);
    cudaGetSymbolAddress(&pk, g_k);
    cudaGetSymbolAddress(&pv, g_v);
    cudaGetSymbolAddress(&pa, g_a);
    cudaGetSymbolAddress(&po, g_o);
    float* x = (float*)px;
    float* q = (float*)pq;
    float* k = (float*)pk;
    float* v = (float*)pv;
    float* a = (float*)pa;
    float* o = (float*)po;

    const long MD = (long)TT * DD;   // per-batch elements of Q/K/V/x
    const long AA = (long)TT * TT;   // per-batch elements of scores

    embed_pe_kernel<<<BB * TT, 256>>>(src, pe, emb, x);

    dim3 gp(DD / 128, (BB * TT) / 128);       // projections: M=2048, N=1024
    dim3 gs(TT / 128, TT / 128, BB);          // attention GEMMs: per batch
    for (int l = 0; l < LL; l++) {
        const long wo = (long)l * DD * DD;
        sgemm128<true, false><<<gp, 256>>>(x, qw + wo, qb + l * DD, q, DD, DD, DD, DD, 0, 0, 0);
        sgemm128<true, false><<<gp, 256>>>(x, kw + wo, kb + l * DD, k, DD, DD, DD, DD, 0, 0, 0);
        sgemm128<true, false><<<gp, 256>>>(x, vw + wo, vb + l * DD, v, DD, DD, DD, DD, 0, 0, 0);
        // scores = Q K^T (unscaled), causal blocks only
        sgemm128<true, true><<<gs, 256>>>(q, k, nullptr, a, DD, DD, DD, TT, MD, MD, AA);
        softmax_kernel<<<dim3(TT, BB), 256>>>(a);
        // o = w @ V (dense: w has exact zeros above diagonal)
        sgemm128<false, false><<<gs, 256>>>(a, v, nullptr, o, TT, TT, DD, DD, AA, MD, MD);
        ln_res_kernel<<<BB * TT, 256>>>(o, lnw + l * DD, lnb + l * DD, x);
    }

    final_ln_kernel<<<BB * TT, 256>>>(x, fw, fb, q);
    dim3 gf(VV / 128, (BB * TT) / 128);       // vocab projection: M=2048, N=32000
    sgemm128<true, false><<<gf, 256>>>(q, dw, db, out, DD, DD, DD, VV, 0, 0, 0);
}